// round 15
// baseline (speedup 1.0000x reference)
#include <cuda_runtime.h>
#include <cuda_fp16.h>
#include <math.h>
#include <stdint.h>

// Problem constants
#define Bn 16
#define Sn 4096
#define Cn 512
#define Kn 5
#define Tn 1024
#define Rn (Cn*Kn)   // 2560
#define Mp (Sn/2)    // 2048 m-pairs per batch

// ---------------- device scratch ----------------
__device__ __align__(16) __half g_xwhi[6ull * Bn * Mp * Cn];
__device__ __align__(16) __half g_xwlo[6ull * Bn * Mp * Cn];
__device__ __align__(16) __half g_wwhi[6 * Cn * Cn];
__device__ __align__(16) __half g_wwlo[6 * Cn * Cn];
__device__ float g_h[(size_t)Bn * Sn * Cn];
__device__ float g_alpha[Bn * Sn];
__device__ float g_csum[Bn * Sn];
__device__ float g_scale[Bn];

__constant__ float c_aw0[6] = {1.f, 1.f, 1.f, 1.f, 1.f, 0.f};   // A^T row 0
__constant__ float c_aw1[6] = {0.f, 1.f, -1.f, 2.f, -2.f, 1.f}; // A^T row 1

// ---------------- helpers ----------------
__device__ __forceinline__ uint32_t smem_u32(const void* p) {
    uint32_t a;
    asm("{ .reg .u64 t; cvta.to.shared.u64 t, %1; cvt.u32.u64 %0, t; }" : "=r"(a) : "l"(p));
    return a;
}
#define SWZ(x) ((x) ^ (((x) >> 3) & 0x70))

__device__ __forceinline__ void cp_async16(uint32_t dst, const void* src) {
    asm volatile("cp.async.cg.shared.global [%0], [%1], 16;"
                 :: "r"(dst), "l"(src) : "memory");
}
__device__ __forceinline__ void cp_commit() {
    asm volatile("cp.async.commit_group;" ::: "memory");
}
__device__ __forceinline__ void cp_wait1() {
    asm volatile("cp.async.wait_group 1;" ::: "memory");
}
__device__ __forceinline__ void cp_wait0() {
    asm volatile("cp.async.wait_group 0;" ::: "memory");
}
__device__ __forceinline__ void ldsm_x4(uint32_t addr, uint32_t& r0, uint32_t& r1,
                                        uint32_t& r2, uint32_t& r3) {
    asm volatile("ldmatrix.sync.aligned.m8n8.x4.shared.b16 {%0,%1,%2,%3}, [%4];"
                 : "=r"(r0), "=r"(r1), "=r"(r2), "=r"(r3) : "r"(addr));
}
__device__ __forceinline__ void mma_f16(float& c0, float& c1, float& c2, float& c3,
                                        uint32_t a0, uint32_t a1, uint32_t a2, uint32_t a3,
                                        uint32_t b0, uint32_t b1) {
    asm volatile(
        "mma.sync.aligned.m16n8k16.row.col.f32.f16.f16.f32 "
        "{%0,%1,%2,%3}, {%4,%5,%6,%7}, {%8,%9}, {%0,%1,%2,%3};"
        : "+f"(c0), "+f"(c1), "+f"(c2), "+f"(c3)
        : "r"(a0), "r"(a1), "r"(a2), "r"(a3), "r"(b0), "r"(b1));
}
__device__ __forceinline__ void split16(float v, __half& h, __half& l) {
    h = __float2half_rn(v);
    l = __float2half_rn(v - __half2float(h));
}

// ---------------- kernel: weight Winograd transform ----------------
__global__ void wino_w(const float* __restrict__ w) {
    int idx = blockIdx.x * 256 + threadIdx.x;   // < 512*512
    int co = idx >> 9;
    int ci = idx & 511;
    const float* wp = w + (size_t)co * Rn + ci * Kn;
    float w0 = wp[0], w1 = wp[1], w2 = wp[2], w3 = wp[3], w4 = wp[4];
    float tw[6];
    tw[0] = w0;
    tw[1] = w0 + w1 + w2 + w3 + w4;
    tw[2] = w0 - w1 + w2 - w3 + w4;
    tw[3] = w0 + 2.f*w1 + 4.f*w2 + 8.f*w3 + 16.f*w4;
    tw[4] = w0 - 2.f*w1 + 4.f*w2 - 8.f*w3 + 16.f*w4;
    tw[5] = w4;
    #pragma unroll
    for (int j = 0; j < 6; j++) {
        __half h, l;
        split16(tw[j], h, l);
        size_t o = ((size_t)(j * Cn + co)) * Cn + ci;
        g_wwhi[o] = h;
        g_wwlo[o] = l;
    }
}

// ---------------- kernel: input Winograd transform ----------------
__global__ void wino_x(const float* __restrict__ x) {
    int idx = blockIdx.x * 256 + threadIdx.x;   // < 16*2048*64
    int ci8 = (idx & 63) * 8;
    int m   = (idx >> 6) & (Mp - 1);
    int b   = idx >> 17;

    float d[6][8];
    #pragma unroll
    for (int r = 0; r < 6; r++) {
        int s = 2 * m - 2 + r;
        if (s >= 0 && s < Sn) {
            const float* src = x + ((size_t)(b * Sn + s)) * Cn + ci8;
            float4 a = *(const float4*)src;
            float4 c = *(const float4*)(src + 4);
            d[r][0]=a.x; d[r][1]=a.y; d[r][2]=a.z; d[r][3]=a.w;
            d[r][4]=c.x; d[r][5]=c.y; d[r][6]=c.z; d[r][7]=c.w;
        } else {
            #pragma unroll
            for (int q = 0; q < 8; q++) d[r][q] = 0.f;
        }
    }

    __half oh[6][8], ol[6][8];
    #pragma unroll
    for (int q = 0; q < 8; q++) {
        float d0=d[0][q], d1=d[1][q], d2=d[2][q], d3=d[3][q], d4=d[4][q], d5=d[5][q];
        float t0 = d0 - 1.25f*d2 + 0.25f*d4;
        float t1 = (2.f/3.f)*(d1 + d2) - (1.f/6.f)*(d3 + d4);
        float t2 = (2.f/3.f)*(d2 - d1) + (1.f/6.f)*(d3 - d4);
        float t3 = (1.f/12.f)*(d3 - d1) + (1.f/24.f)*(d4 - d2);
        float t4 = (1.f/12.f)*(d1 - d3) + (1.f/24.f)*(d4 - d2);
        float t5 = 4.f*d1 - 5.f*d3 + d5;
        split16(t0, oh[0][q], ol[0][q]);
        split16(t1, oh[1][q], ol[1][q]);
        split16(t2, oh[2][q], ol[2][q]);
        split16(t3, oh[3][q], ol[3][q]);
        split16(t4, oh[4][q], ol[4][q]);
        split16(t5, oh[5][q], ol[5][q]);
    }
    #pragma unroll
    for (int j = 0; j < 6; j++) {
        size_t o = ((size_t)((j * Bn + b) * Mp + m)) * Cn + ci8;
        *(uint4*)(g_xwhi + o) = *(uint4*)oh[j];
        *(uint4*)(g_xwlo + o) = *(uint4*)ol[j];
    }
}

// ---------------- Winograd GEMM: CTA tile 64 m-pairs x 128 co ----------------
// 48 chunk-iters (6 j x 8 K-chunks of 64 ci). 8 warps all along N; warp tile 64x16.
// Per-thread acc: 3 x 32 floats (no spills). accJ folded into acc0/acc1 via A^T.
#define ST_AW 8192          // A: 64 rows x 128B (each of hi, lo)
#define ST_BW 16384         // B: 128 rows x 128B (each of hi, lo)
#define STG_W (2*ST_AW + 2*ST_BW)   // 49152
#define SMEM_W (2*STG_W)            // 98304
#define NCC 48

__global__ __launch_bounds__(256, 1)
void conv_wino(const float* __restrict__ cbias) {
    extern __shared__ char smem[];
    const uint32_t sbase = smem_u32(smem);
    const int tid  = threadIdx.x;
    const int lane = tid & 31;
    const int wid  = tid >> 5;
    const int b     = blockIdx.z;
    const int mBase = blockIdx.x * 64;    // m-pair base
    const int nBase = blockIdx.y * 128;   // co base
    const int nW = wid * 16;              // warp's 16-co slice

    const uint4* xwhi = (const uint4*)g_xwhi;
    const uint4* xwlo = (const uint4*)g_xwlo;
    const uint4* wwhi = (const uint4*)g_wwhi;
    const uint4* wwlo = (const uint4*)g_wwlo;

    auto load_chunk = [&](int cc) {
        const int j   = cc >> 3;
        const int u0  = (cc & 7) * 8;     // uint4 offset within 512-ci row
        const uint32_t stOff = sbase + (cc & 1) * STG_W;
        // A: 64 rows x 64 ci, hi+lo: 1024 uint4, 4/thread
        #pragma unroll
        for (int i = 0; i < 4; i++) {
            int q   = tid + (i << 8);
            int a2  = q >> 9;
            int rem = q & 511;
            int row = rem >> 3, p = rem & 7;
            const uint4* src = a2 ? xwlo : xwhi;
            cp_async16(stOff + a2 * ST_AW + SWZ(row * 128 + p * 16),
                       src + ((size_t)((j * Bn + b) * Mp + mBase + row)) * 64 + u0 + p);
        }
        // B: 128 rows x 64 ci, hi+lo: 2048 uint4, 8/thread
        #pragma unroll
        for (int i = 0; i < 8; i++) {
            int q   = tid + (i << 8);
            int a2  = q >> 10;
            int rem = q & 1023;
            int row = rem >> 3, p = rem & 7;
            const uint4* src = a2 ? wwlo : wwhi;
            cp_async16(stOff + 2 * ST_AW + a2 * ST_BW + SWZ(row * 128 + p * 16),
                       src + ((size_t)(j * Cn + nBase + row)) * 64 + u0 + p);
        }
        cp_commit();
    };

    float accJ[4][2][4], acc0[4][2][4], acc1[4][2][4];
    #pragma unroll
    for (int i = 0; i < 4; i++)
        #pragma unroll
        for (int n = 0; n < 2; n++)
            #pragma unroll
            for (int k = 0; k < 4; k++) {
                accJ[i][n][k] = 0.f; acc0[i][n][k] = 0.f; acc1[i][n][k] = 0.f;
            }

    load_chunk(0);
    load_chunk(1);

    const int aRow = (lane & 15);
    const int aSub = (lane >> 4) * 16;
    const int bRow = (lane & 7) + ((lane & 16) >> 1);
    const int bSub = ((lane >> 3) & 1) * 16;

    for (int cc = 0; cc < NCC; cc++) {
        if (cc == NCC - 1) cp_wait0(); else cp_wait1();
        __syncthreads();

        const uint32_t aBase = sbase + (cc & 1) * STG_W;
        const uint32_t bBase = aBase + 2 * ST_AW;

        #pragma unroll
        for (int kk = 0; kk < 4; kk++) {
            const int kb = kk * 32;
            uint32_t ah[4][4], al[4][4];
            #pragma unroll
            for (int mt = 0; mt < 4; mt++) {
                int row = mt * 16 + aRow;
                uint32_t off = SWZ(row * 128 + kb + aSub);
                ldsm_x4(aBase + off,         ah[mt][0], ah[mt][1], ah[mt][2], ah[mt][3]);
                ldsm_x4(aBase + ST_AW + off, al[mt][0], al[mt][1], al[mt][2], al[mt][3]);
            }
            uint32_t bh[2][2], bl[2][2];
            {
                int row = nW + bRow;
                uint32_t off = SWZ(row * 128 + kb + bSub);
                ldsm_x4(bBase + off,         bh[0][0], bh[0][1], bh[1][0], bh[1][1]);
                ldsm_x4(bBase + ST_BW + off, bl[0][0], bl[0][1], bl[1][0], bl[1][1]);
            }
            #pragma unroll
            for (int mt = 0; mt < 4; mt++)
                #pragma unroll
                for (int n = 0; n < 2; n++) {
                    float* cc2 = accJ[mt][n];
                    mma_f16(cc2[0], cc2[1], cc2[2], cc2[3],
                            ah[mt][0], ah[mt][1], ah[mt][2], ah[mt][3],
                            bh[n][0], bh[n][1]);
                }
            #pragma unroll
            for (int mt = 0; mt < 4; mt++)
                #pragma unroll
                for (int n = 0; n < 2; n++) {
                    float* cc2 = accJ[mt][n];
                    mma_f16(cc2[0], cc2[1], cc2[2], cc2[3],
                            ah[mt][0], ah[mt][1], ah[mt][2], ah[mt][3],
                            bl[n][0], bl[n][1]);
                }
            #pragma unroll
            for (int mt = 0; mt < 4; mt++)
                #pragma unroll
                for (int n = 0; n < 2; n++) {
                    float* cc2 = accJ[mt][n];
                    mma_f16(cc2[0], cc2[1], cc2[2], cc2[3],
                            al[mt][0], al[mt][1], al[mt][2], al[mt][3],
                            bh[n][0], bh[n][1]);
                }
        }

        if ((cc & 7) == 7) {
            const int j = cc >> 3;
            const float w0 = c_aw0[j], w1 = c_aw1[j];
            #pragma unroll
            for (int mt = 0; mt < 4; mt++)
                #pragma unroll
                for (int n = 0; n < 2; n++)
                    #pragma unroll
                    for (int k = 0; k < 4; k++) {
                        float v = accJ[mt][n][k];
                        acc0[mt][n][k] += w0 * v;
                        acc1[mt][n][k] += w1 * v;
                        accJ[mt][n][k] = 0.f;
                    }
        }

        __syncthreads();
        if (cc + 2 < NCC) load_chunk(cc + 2);
    }

    // ---- epilogue: H[2m] = acc0 + bias, H[2m+1] = acc1 + bias ----
    #pragma unroll
    for (int n = 0; n < 2; n++) {
        const int col = nBase + nW + n * 8 + (lane & 3) * 2;
        const float b0 = cbias[col], b1 = cbias[col + 1];
        #pragma unroll
        for (int mt = 0; mt < 4; mt++) {
            const int mp = mBase + mt * 16 + (lane >> 2);   // m-pair index
            float* p0 = g_h + ((size_t)(b * Sn + 2 * mp)) * Cn + col;
            p0[0]           = acc0[mt][n][0] + b0;  p0[1]           = acc0[mt][n][1] + b1;
            p0[Cn]          = acc1[mt][n][0] + b0;  p0[Cn + 1]      = acc1[mt][n][1] + b1;
            p0[16 * Cn]     = acc0[mt][n][2] + b0;  p0[16 * Cn + 1] = acc0[mt][n][3] + b1;
            p0[17 * Cn]     = acc1[mt][n][2] + b0;  p0[17 * Cn + 1] = acc1[mt][n][3] + b1;
        }
    }
}

// ---------------- kernel: LayerNorm + ReLU + Linear + sigmoid (float4 loads) ----
__global__ void ln_alpha(const float* __restrict__ lng, const float* __restrict__ lnb,
                         const float* __restrict__ lw,  const float* __restrict__ lb,
                         float* __restrict__ alpha_out) {
    const int warp = threadIdx.x >> 5;
    const int lane = threadIdx.x & 31;
    const int row  = blockIdx.x * 8 + warp;
    const float4* hr = (const float4*)(g_h + (size_t)row * Cn);
    const float4* g4 = (const float4*)lng;
    const float4* b4 = (const float4*)lnb;
    const float4* w4 = (const float4*)lw;

    float4 v[4];
    float sum = 0.f;
    #pragma unroll
    for (int j = 0; j < 4; j++) {
        v[j] = hr[lane + j * 32];
        sum += (v[j].x + v[j].y) + (v[j].z + v[j].w);
    }
    #pragma unroll
    for (int o = 16; o; o >>= 1) sum += __shfl_xor_sync(0xffffffffu, sum, o);
    const float mu = sum * (1.0f / Cn);

    float vs = 0.f;
    #pragma unroll
    for (int j = 0; j < 4; j++) {
        float dx = v[j].x - mu, dy = v[j].y - mu, dz = v[j].z - mu, dw = v[j].w - mu;
        vs += dx * dx + dy * dy + dz * dz + dw * dw;
    }
    #pragma unroll
    for (int o = 16; o; o >>= 1) vs += __shfl_xor_sync(0xffffffffu, vs, o);
    const float rstd = rsqrtf(vs * (1.0f / Cn) + 1e-5f);

    float dot = 0.f;
    #pragma unroll
    for (int j = 0; j < 4; j++) {
        const int c4 = lane + j * 32;
        float4 gg = g4[c4], bb = b4[c4], ww = w4[c4];
        float h0 = fmaxf((v[j].x - mu) * rstd * gg.x + bb.x, 0.f);
        float h1 = fmaxf((v[j].y - mu) * rstd * gg.y + bb.y, 0.f);
        float h2 = fmaxf((v[j].z - mu) * rstd * gg.z + bb.z, 0.f);
        float h3 = fmaxf((v[j].w - mu) * rstd * gg.w + bb.w, 0.f);
        dot += h0 * ww.x + h1 * ww.y + h2 * ww.z + h3 * ww.w;
    }
    #pragma unroll
    for (int o = 16; o; o >>= 1) dot += __shfl_xor_sync(0xffffffffu, dot, o);

    if (lane == 0) {
        float a = 1.0f / (1.0f + expf(-(dot + lb[0])));
        g_alpha[row]   = a;
        alpha_out[row] = a;
    }
}

// ---------------- kernel: per-batch alpha-sum, rescale, inclusive cumsum ----------------
__global__ void scan_cif(const int* __restrict__ tlen) {
    __shared__ float wsum[32];
    __shared__ float woff[32];
    __shared__ float sscale;

    const int b   = blockIdx.x;
    const int tid = threadIdx.x;
    const int wid  = tid >> 5;
    const int lane = tid & 31;
    const float* ar = g_alpha + b * Sn;

    float v0 = ar[tid * 4 + 0], v1 = ar[tid * 4 + 1];
    float v2 = ar[tid * 4 + 2], v3 = ar[tid * 4 + 3];
    float tsum = v0 + v1 + v2 + v3;

    float r = tsum;
    #pragma unroll
    for (int o = 16; o; o >>= 1) r += __shfl_xor_sync(0xffffffffu, r, o);
    if (lane == 0) wsum[wid] = r;
    __syncthreads();
    if (tid == 0) {
        float a = 0.f;
        for (int i = 0; i < 32; i++) a += wsum[i];
        sscale = ((float)tlen[b] + 1e-4f) / a;
    }
    __syncthreads();
    const float sc = sscale;

    float p0 = v0 * sc;
    float p1 = p0 + v1 * sc;
    float p2 = p1 + v2 * sc;
    float p3 = p2 + v3 * sc;

    float inc = p3;
    #pragma unroll
    for (int o = 1; o < 32; o <<= 1) {
        float t = __shfl_up_sync(0xffffffffu, inc, o);
        if (lane >= o) inc += t;
    }
    if (lane == 31) wsum[wid] = inc;
    __syncthreads();
    if (tid < 32) {
        float t = wsum[tid];
        float i2 = t;
        #pragma unroll
        for (int o = 1; o < 32; o <<= 1) {
            float u = __shfl_up_sync(0xffffffffu, i2, o);
            if (tid >= o) i2 += u;
        }
        woff[tid] = i2 - t;
    }
    __syncthreads();

    const float off = woff[wid] + (inc - p3);
    float* cs = g_csum + b * Sn + tid * 4;
    cs[0] = off + p0; cs[1] = off + p1; cs[2] = off + p2; cs[3] = off + p3;
    if (tid == 0) g_scale[b] = sc;
}

// ---------------- kernel: CIF gather v2 (warp-parallel weight precompute) --------
__global__ void gather_cif(const float* __restrict__ x, float* __restrict__ out) {
    const int t = blockIdx.x;
    const int b = blockIdx.y;
    const float* cs = g_csum + b * Sn;
    const float sc = g_scale[b];
    const int tid = threadIdx.x;

    const float loV = (float)(t - 1), hiV = (float)(t + 1);
    int l = 0, r = Sn;
    while (l < r) { int m = (l + r) >> 1; if (cs[m] < loV) l = m + 1; else r = m; }
    const int lo = l;
    l = lo; r = Sn;
    while (l < r) { int m = (l + r) >> 1; if (cs[m] < hiV) l = m + 1; else r = m; }
    const int hi = min(l + 1, Sn);

    __shared__ float wbuf[128];
    const int tid4 = tid * 4;
    float4 acc = make_float4(0.f, 0.f, 0.f, 0.f);

    for (int base = lo; base < hi; base += 128) {
        int s = base + tid;
        float w = 0.f;
        if (s < hi) {
            float c1 = cs[s];
            float c0 = s ? cs[s - 1] : 0.f;
            int ri = min((int)c1, Tn);
            int li = s ? min((int)c0, Tn) : 0;
            int fire = ri - li;
            int extra = fire - 1 > 0 ? fire - 1 : 0;
            float rw = fire > 0 ? c1 - (float)ri : 0.f;
            if (fire > 0 && ri == t) w += rw;
            if (li == t) w += g_alpha[b * Sn + s] * sc - rw - (float)extra;
            if (extra > 0 && li + 1 == t) w += 1.f;
        }
        wbuf[tid] = w;
        __syncthreads();

        const int nend = min(hi - base, 128);
        for (int j = 0; j < nend; j++) {
            float w2 = wbuf[j];
            if (w2 != 0.f) {
                float4 xv = *(const float4*)(x + ((size_t)(b * Sn + base + j)) * Cn + tid4);
                acc.x += w2 * xv.x; acc.y += w2 * xv.y;
                acc.z += w2 * xv.z; acc.w += w2 * xv.w;
            }
        }
        __syncthreads();
    }
    *(float4*)(out + ((size_t)(b * Tn + t)) * Cn + tid4) = acc;
}

// ---------------- launch ----------------
extern "C" void kernel_launch(void* const* d_in, const int* in_sizes, int n_in,
                              void* d_out, int out_size) {
    const float* x      = (const float*)d_in[0];
    const int*   tlen   = (const int*)d_in[2];
    const float* conv_w = (const float*)d_in[4];
    const float* conv_b = (const float*)d_in[5];
    const float* ln_g   = (const float*)d_in[6];
    const float* ln_b   = (const float*)d_in[7];
    const float* lin_w  = (const float*)d_in[8];
    const float* lin_b  = (const float*)d_in[9];

    float* out_main  = (float*)d_out;                          // [B,T,C]
    float* out_alpha = (float*)d_out + (size_t)Bn * Tn * Cn;   // [B,S]

    static bool attr_set = false;
    if (!attr_set) {
        cudaFuncSetAttribute(conv_wino, cudaFuncAttributeMaxDynamicSharedMemorySize, SMEM_W);
        attr_set = true;
    }

    wino_w<<<(Cn * Cn) / 256, 256>>>(conv_w);
    wino_x<<<(Bn * Mp * 64) / 256, 256>>>(x);

    conv_wino<<<dim3(Mp / 64, Cn / 128, Bn), 256, SMEM_W>>>(conv_b);

    ln_alpha<<<(Bn * Sn) / 8, 256>>>(ln_g, ln_b, lin_w, lin_b, out_alpha);
    scan_cif<<<Bn, 1024>>>(tlen);
    gather_cif<<<dim3(Tn, Bn), 128>>>(x, out_main);
}

// round 16
// speedup vs baseline: 1.0899x; 1.0899x over previous
#include <cuda_runtime.h>
#include <cuda_fp16.h>
#include <math.h>
#include <stdint.h>

// Problem constants
#define Bn 16
#define Sn 4096
#define Cn 512
#define Kn 5
#define Tn 1024
#define Rn (Cn*Kn)   // 2560
#define Mp (Sn/2)    // 2048 m-pairs per batch

// ---------------- device scratch ----------------
__device__ __align__(16) __half g_xwhi[6ull * Bn * Mp * Cn];
__device__ __align__(16) __half g_xwlo[6ull * Bn * Mp * Cn];
__device__ __align__(16) __half g_wwhi[6 * Cn * Cn];
__device__ __align__(16) __half g_wwlo[6 * Cn * Cn];
__device__ float g_h[(size_t)Bn * Sn * Cn];
__device__ float g_alpha[Bn * Sn];
__device__ float g_csum[Bn * Sn];
__device__ float g_scale[Bn];

__constant__ float c_aw0[6] = {1.f, 1.f, 1.f, 1.f, 1.f, 0.f};   // A^T row 0
__constant__ float c_aw1[6] = {0.f, 1.f, -1.f, 2.f, -2.f, 1.f}; // A^T row 1

// ---------------- helpers ----------------
__device__ __forceinline__ uint32_t smem_u32(const void* p) {
    uint32_t a;
    asm("{ .reg .u64 t; cvta.to.shared.u64 t, %1; cvt.u32.u64 %0, t; }" : "=r"(a) : "l"(p));
    return a;
}
#define SWZ(x) ((x) ^ (((x) >> 3) & 0x70))

__device__ __forceinline__ void cp_async16(uint32_t dst, const void* src) {
    asm volatile("cp.async.cg.shared.global [%0], [%1], 16;"
                 :: "r"(dst), "l"(src) : "memory");
}
__device__ __forceinline__ void cp_commit() {
    asm volatile("cp.async.commit_group;" ::: "memory");
}
__device__ __forceinline__ void cp_wait1() {
    asm volatile("cp.async.wait_group 1;" ::: "memory");
}
__device__ __forceinline__ void cp_wait0() {
    asm volatile("cp.async.wait_group 0;" ::: "memory");
}
__device__ __forceinline__ void ldsm_x4(uint32_t addr, uint32_t& r0, uint32_t& r1,
                                        uint32_t& r2, uint32_t& r3) {
    asm volatile("ldmatrix.sync.aligned.m8n8.x4.shared.b16 {%0,%1,%2,%3}, [%4];"
                 : "=r"(r0), "=r"(r1), "=r"(r2), "=r"(r3) : "r"(addr));
}
__device__ __forceinline__ void mma_f16(float& c0, float& c1, float& c2, float& c3,
                                        uint32_t a0, uint32_t a1, uint32_t a2, uint32_t a3,
                                        uint32_t b0, uint32_t b1) {
    asm volatile(
        "mma.sync.aligned.m16n8k16.row.col.f32.f16.f16.f32 "
        "{%0,%1,%2,%3}, {%4,%5,%6,%7}, {%8,%9}, {%0,%1,%2,%3};"
        : "+f"(c0), "+f"(c1), "+f"(c2), "+f"(c3)
        : "r"(a0), "r"(a1), "r"(a2), "r"(a3), "r"(b0), "r"(b1));
}
__device__ __forceinline__ void split16(float v, __half& h, __half& l) {
    h = __float2half_rn(v);
    l = __float2half_rn(v - __half2float(h));
}

// ---------------- kernel: merged Winograd transforms (x blocks, then w blocks) ----
#define XWBLK (Bn * Mp * 64 / 256)     // 8192 blocks for x transform
#define WWBLK ((Cn * Cn) / 256)        // 1024 blocks for w transform

__global__ void wino_xw(const float* __restrict__ x, const float* __restrict__ w) {
    if (blockIdx.x < XWBLK) {
        // ---- input transform: X̂_j[b][m][ci] over d = x[2m-2 .. 2m+3][ci] ----
        int idx = blockIdx.x * 256 + threadIdx.x;   // < 16*2048*64
        int ci8 = (idx & 63) * 8;
        int m   = (idx >> 6) & (Mp - 1);
        int b   = idx >> 17;

        float d[6][8];
        #pragma unroll
        for (int r = 0; r < 6; r++) {
            int s = 2 * m - 2 + r;
            if (s >= 0 && s < Sn) {
                const float* src = x + ((size_t)(b * Sn + s)) * Cn + ci8;
                float4 a = *(const float4*)src;
                float4 c = *(const float4*)(src + 4);
                d[r][0]=a.x; d[r][1]=a.y; d[r][2]=a.z; d[r][3]=a.w;
                d[r][4]=c.x; d[r][5]=c.y; d[r][6]=c.z; d[r][7]=c.w;
            } else {
                #pragma unroll
                for (int q = 0; q < 8; q++) d[r][q] = 0.f;
            }
        }

        __half oh[6][8], ol[6][8];
        #pragma unroll
        for (int q = 0; q < 8; q++) {
            float d0=d[0][q], d1=d[1][q], d2=d[2][q], d3=d[3][q], d4=d[4][q], d5=d[5][q];
            float t0 = d0 - 1.25f*d2 + 0.25f*d4;
            float t1 = (2.f/3.f)*(d1 + d2) - (1.f/6.f)*(d3 + d4);
            float t2 = (2.f/3.f)*(d2 - d1) + (1.f/6.f)*(d3 - d4);
            float t3 = (1.f/12.f)*(d3 - d1) + (1.f/24.f)*(d4 - d2);
            float t4 = (1.f/12.f)*(d1 - d3) + (1.f/24.f)*(d4 - d2);
            float t5 = 4.f*d1 - 5.f*d3 + d5;
            split16(t0, oh[0][q], ol[0][q]);
            split16(t1, oh[1][q], ol[1][q]);
            split16(t2, oh[2][q], ol[2][q]);
            split16(t3, oh[3][q], ol[3][q]);
            split16(t4, oh[4][q], ol[4][q]);
            split16(t5, oh[5][q], ol[5][q]);
        }
        #pragma unroll
        for (int j = 0; j < 6; j++) {
            size_t o = ((size_t)((j * Bn + b) * Mp + m)) * Cn + ci8;
            *(uint4*)(g_xwhi + o) = *(uint4*)oh[j];
            *(uint4*)(g_xwlo + o) = *(uint4*)ol[j];
        }
    } else {
        // ---- weight transform: Ŵ_j[co][ci] = G[j] · w[co][ci][0..4] ----
        int idx = (blockIdx.x - XWBLK) * 256 + threadIdx.x;   // < 512*512
        int co = idx >> 9;
        int ci = idx & 511;
        const float* wp = w + (size_t)co * Rn + ci * Kn;
        float w0 = wp[0], w1 = wp[1], w2 = wp[2], w3 = wp[3], w4 = wp[4];
        float tw[6];
        tw[0] = w0;
        tw[1] = w0 + w1 + w2 + w3 + w4;
        tw[2] = w0 - w1 + w2 - w3 + w4;
        tw[3] = w0 + 2.f*w1 + 4.f*w2 + 8.f*w3 + 16.f*w4;
        tw[4] = w0 - 2.f*w1 + 4.f*w2 - 8.f*w3 + 16.f*w4;
        tw[5] = w4;
        #pragma unroll
        for (int j = 0; j < 6; j++) {
            __half h, l;
            split16(tw[j], h, l);
            size_t o = ((size_t)(j * Cn + co)) * Cn + ci;
            g_wwhi[o] = h;
            g_wwlo[o] = l;
        }
    }
}

// ---------------- Winograd GEMM (R14 config: 128 m-pairs x 128 co) ----------------
// 48 chunk-iters (6 j x 8 K-chunks of 64 ci). 8 warps 2(M) x 4(N); warp tile 64x32.
// accJ per-j, folded into acc0/acc1 via A^T weights every 8 chunks.
#define ST 16384            // each of Ah, Al, Bh, Bl: 128 rows x 128B
#define STG_W (4*ST)        // 65536
#define SMEM_W (2*STG_W)    // 131072
#define NCC 48

__global__ __launch_bounds__(256, 1)
void conv_wino(const float* __restrict__ cbias) {
    extern __shared__ char smem[];
    const uint32_t sbase = smem_u32(smem);
    const int tid  = threadIdx.x;
    const int lane = tid & 31;
    const int wid  = tid >> 5;
    const int b     = blockIdx.z;
    const int mBase = blockIdx.x * 128;   // m-pair base
    const int nBase = blockIdx.y * 128;   // co base
    const int mW = (wid >> 2) * 64;
    const int nW = (wid & 3) * 32;

    const uint4* xwhi = (const uint4*)g_xwhi;
    const uint4* xwlo = (const uint4*)g_xwlo;
    const uint4* wwhi = (const uint4*)g_wwhi;
    const uint4* wwlo = (const uint4*)g_wwlo;

    auto load_chunk = [&](int cc) {
        const int j   = cc >> 3;
        const int u0  = (cc & 7) * 8;     // uint4 offset within 512-ci row
        const uint32_t stOff = sbase + (cc & 1) * STG_W;
        // A: 128 m-pair rows x 64 ci, hi+lo: 2048 uint4, 8/thread
        #pragma unroll
        for (int i = 0; i < 8; i++) {
            int q   = tid + (i << 8);
            int a2  = q >> 10;
            int rem = q & 1023;
            int row = rem >> 3, p = rem & 7;
            const uint4* src = a2 ? xwlo : xwhi;
            cp_async16(stOff + a2 * ST + SWZ(row * 128 + p * 16),
                       src + ((size_t)((j * Bn + b) * Mp + mBase + row)) * 64 + u0 + p);
        }
        // B: 128 co rows x 64 ci, hi+lo: 2048 uint4, 8/thread
        #pragma unroll
        for (int i = 0; i < 8; i++) {
            int q   = tid + (i << 8);
            int a2  = q >> 10;
            int rem = q & 1023;
            int row = rem >> 3, p = rem & 7;
            const uint4* src = a2 ? wwlo : wwhi;
            cp_async16(stOff + 2 * ST + a2 * ST + SWZ(row * 128 + p * 16),
                       src + ((size_t)(j * Cn + nBase + row)) * 64 + u0 + p);
        }
        cp_commit();
    };

    float accJ[4][4][4], acc0[4][4][4], acc1[4][4][4];
    #pragma unroll
    for (int i = 0; i < 4; i++)
        #pragma unroll
        for (int n = 0; n < 4; n++)
            #pragma unroll
            for (int k = 0; k < 4; k++) {
                accJ[i][n][k] = 0.f; acc0[i][n][k] = 0.f; acc1[i][n][k] = 0.f;
            }

    load_chunk(0);
    load_chunk(1);

    const int aRow = (lane & 15);
    const int aSub = (lane >> 4) * 16;
    const int bRow = (lane & 7) + ((lane & 16) >> 1);
    const int bSub = ((lane >> 3) & 1) * 16;

    for (int cc = 0; cc < NCC; cc++) {
        if (cc == NCC - 1) cp_wait0(); else cp_wait1();
        __syncthreads();

        const uint32_t aBase = sbase + (cc & 1) * STG_W;
        const uint32_t bBase = aBase + 2 * ST;

        #pragma unroll
        for (int kk = 0; kk < 4; kk++) {
            const int kb = kk * 32;
            uint32_t ah[4][4], al[4][4];
            #pragma unroll
            for (int mt = 0; mt < 4; mt++) {
                int row = mW + mt * 16 + aRow;
                uint32_t off = SWZ(row * 128 + kb + aSub);
                ldsm_x4(aBase + off,      ah[mt][0], ah[mt][1], ah[mt][2], ah[mt][3]);
                ldsm_x4(aBase + ST + off, al[mt][0], al[mt][1], al[mt][2], al[mt][3]);
            }
            #pragma unroll
            for (int nt2 = 0; nt2 < 2; nt2++) {
                uint32_t bh[2][2], bl[2][2];
                int row = nW + nt2 * 16 + bRow;
                uint32_t off = SWZ(row * 128 + kb + bSub);
                ldsm_x4(bBase + off,      bh[0][0], bh[0][1], bh[1][0], bh[1][1]);
                ldsm_x4(bBase + ST + off, bl[0][0], bl[0][1], bl[1][0], bl[1][1]);
                #pragma unroll
                for (int mt = 0; mt < 4; mt++)
                    #pragma unroll
                    for (int n = 0; n < 2; n++) {
                        float* cc2 = accJ[mt][nt2 * 2 + n];
                        mma_f16(cc2[0], cc2[1], cc2[2], cc2[3],
                                ah[mt][0], ah[mt][1], ah[mt][2], ah[mt][3],
                                bh[n][0], bh[n][1]);
                    }
                #pragma unroll
                for (int mt = 0; mt < 4; mt++)
                    #pragma unroll
                    for (int n = 0; n < 2; n++) {
                        float* cc2 = accJ[mt][nt2 * 2 + n];
                        mma_f16(cc2[0], cc2[1], cc2[2], cc2[3],
                                ah[mt][0], ah[mt][1], ah[mt][2], ah[mt][3],
                                bl[n][0], bl[n][1]);
                    }
                #pragma unroll
                for (int mt = 0; mt < 4; mt++)
                    #pragma unroll
                    for (int n = 0; n < 2; n++) {
                        float* cc2 = accJ[mt][nt2 * 2 + n];
                        mma_f16(cc2[0], cc2[1], cc2[2], cc2[3],
                                al[mt][0], al[mt][1], al[mt][2], al[mt][3],
                                bh[n][0], bh[n][1]);
                    }
            }
        }

        // fold completed j-GEMM into output accumulators (A^T combine)
        if ((cc & 7) == 7) {
            const int j = cc >> 3;
            const float w0 = c_aw0[j], w1 = c_aw1[j];
            #pragma unroll
            for (int mt = 0; mt < 4; mt++)
                #pragma unroll
                for (int n = 0; n < 4; n++)
                    #pragma unroll
                    for (int k = 0; k < 4; k++) {
                        float v = accJ[mt][n][k];
                        acc0[mt][n][k] += w0 * v;
                        acc1[mt][n][k] += w1 * v;
                        accJ[mt][n][k] = 0.f;
                    }
        }

        __syncthreads();
        if (cc + 2 < NCC) load_chunk(cc + 2);
    }

    // ---- epilogue: H[2m] = acc0 + bias, H[2m+1] = acc1 + bias ----
    #pragma unroll
    for (int nt = 0; nt < 4; nt++) {
        const int col = nBase + nW + nt * 8 + (lane & 3) * 2;
        const float b0 = cbias[col], b1 = cbias[col + 1];
        #pragma unroll
        for (int mt = 0; mt < 4; mt++) {
            const int mp = mBase + mW + mt * 16 + (lane >> 2);   // m-pair index
            float* p0 = g_h + ((size_t)(b * Sn + 2 * mp)) * Cn + col;
            p0[0]            = acc0[mt][nt][0] + b0;  p0[1]            = acc0[mt][nt][1] + b1;
            p0[Cn]           = acc1[mt][nt][0] + b0;  p0[Cn + 1]       = acc1[mt][nt][1] + b1;
            p0[16 * Cn]      = acc0[mt][nt][2] + b0;  p0[16 * Cn + 1]  = acc0[mt][nt][3] + b1;
            p0[17 * Cn]      = acc1[mt][nt][2] + b0;  p0[17 * Cn + 1]  = acc1[mt][nt][3] + b1;
        }
    }
}

// ---------------- kernel: LayerNorm + ReLU + Linear + sigmoid (float4 loads) ----
__global__ void ln_alpha(const float* __restrict__ lng, const float* __restrict__ lnb,
                         const float* __restrict__ lw,  const float* __restrict__ lb,
                         float* __restrict__ alpha_out) {
    const int warp = threadIdx.x >> 5;
    const int lane = threadIdx.x & 31;
    const int row  = blockIdx.x * 8 + warp;
    const float4* hr = (const float4*)(g_h + (size_t)row * Cn);
    const float4* g4 = (const float4*)lng;
    const float4* b4 = (const float4*)lnb;
    const float4* w4 = (const float4*)lw;

    float4 v[4];
    float sum = 0.f;
    #pragma unroll
    for (int j = 0; j < 4; j++) {
        v[j] = hr[lane + j * 32];
        sum += (v[j].x + v[j].y) + (v[j].z + v[j].w);
    }
    #pragma unroll
    for (int o = 16; o; o >>= 1) sum += __shfl_xor_sync(0xffffffffu, sum, o);
    const float mu = sum * (1.0f / Cn);

    float vs = 0.f;
    #pragma unroll
    for (int j = 0; j < 4; j++) {
        float dx = v[j].x - mu, dy = v[j].y - mu, dz = v[j].z - mu, dw = v[j].w - mu;
        vs += dx * dx + dy * dy + dz * dz + dw * dw;
    }
    #pragma unroll
    for (int o = 16; o; o >>= 1) vs += __shfl_xor_sync(0xffffffffu, vs, o);
    const float rstd = rsqrtf(vs * (1.0f / Cn) + 1e-5f);

    float dot = 0.f;
    #pragma unroll
    for (int j = 0; j < 4; j++) {
        const int c4 = lane + j * 32;
        float4 gg = g4[c4], bb = b4[c4], ww = w4[c4];
        float h0 = fmaxf((v[j].x - mu) * rstd * gg.x + bb.x, 0.f);
        float h1 = fmaxf((v[j].y - mu) * rstd * gg.y + bb.y, 0.f);
        float h2 = fmaxf((v[j].z - mu) * rstd * gg.z + bb.z, 0.f);
        float h3 = fmaxf((v[j].w - mu) * rstd * gg.w + bb.w, 0.f);
        dot += h0 * ww.x + h1 * ww.y + h2 * ww.z + h3 * ww.w;
    }
    #pragma unroll
    for (int o = 16; o; o >>= 1) dot += __shfl_xor_sync(0xffffffffu, dot, o);

    if (lane == 0) {
        float a = 1.0f / (1.0f + expf(-(dot + lb[0])));
        g_alpha[row]   = a;
        alpha_out[row] = a;
    }
}

// ---------------- kernel: per-batch alpha-sum, rescale, inclusive cumsum ----------------
__global__ void scan_cif(const int* __restrict__ tlen) {
    __shared__ float wsum[32];
    __shared__ float woff[32];
    __shared__ float sscale;

    const int b   = blockIdx.x;
    const int tid = threadIdx.x;
    const int wid  = tid >> 5;
    const int lane = tid & 31;
    const float* ar = g_alpha + b * Sn;

    float v0 = ar[tid * 4 + 0], v1 = ar[tid * 4 + 1];
    float v2 = ar[tid * 4 + 2], v3 = ar[tid * 4 + 3];
    float tsum = v0 + v1 + v2 + v3;

    float r = tsum;
    #pragma unroll
    for (int o = 16; o; o >>= 1) r += __shfl_xor_sync(0xffffffffu, r, o);
    if (lane == 0) wsum[wid] = r;
    __syncthreads();
    if (tid == 0) {
        float a = 0.f;
        for (int i = 0; i < 32; i++) a += wsum[i];
        sscale = ((float)tlen[b] + 1e-4f) / a;
    }
    __syncthreads();
    const float sc = sscale;

    float p0 = v0 * sc;
    float p1 = p0 + v1 * sc;
    float p2 = p1 + v2 * sc;
    float p3 = p2 + v3 * sc;

    float inc = p3;
    #pragma unroll
    for (int o = 1; o < 32; o <<= 1) {
        float t = __shfl_up_sync(0xffffffffu, inc, o);
        if (lane >= o) inc += t;
    }
    if (lane == 31) wsum[wid] = inc;
    __syncthreads();
    if (tid < 32) {
        float t = wsum[tid];
        float i2 = t;
        #pragma unroll
        for (int o = 1; o < 32; o <<= 1) {
            float u = __shfl_up_sync(0xffffffffu, i2, o);
            if (tid >= o) i2 += u;
        }
        woff[tid] = i2 - t;
    }
    __syncthreads();

    const float off = woff[wid] + (inc - p3);
    float* cs = g_csum + b * Sn + tid * 4;
    cs[0] = off + p0; cs[1] = off + p1; cs[2] = off + p2; cs[3] = off + p3;
    if (tid == 0) g_scale[b] = sc;
}

// ---------------- kernel: CIF gather v2 (warp-parallel weight precompute) --------
__global__ void gather_cif(const float* __restrict__ x, float* __restrict__ out) {
    const int t = blockIdx.x;
    const int b = blockIdx.y;
    const float* cs = g_csum + b * Sn;
    const float sc = g_scale[b];
    const int tid = threadIdx.x;

    const float loV = (float)(t - 1), hiV = (float)(t + 1);
    int l = 0, r = Sn;
    while (l < r) { int m = (l + r) >> 1; if (cs[m] < loV) l = m + 1; else r = m; }
    const int lo = l;
    l = lo; r = Sn;
    while (l < r) { int m = (l + r) >> 1; if (cs[m] < hiV) l = m + 1; else r = m; }
    const int hi = min(l + 1, Sn);

    __shared__ float wbuf[128];
    const int tid4 = tid * 4;
    float4 acc = make_float4(0.f, 0.f, 0.f, 0.f);

    for (int base = lo; base < hi; base += 128) {
        int s = base + tid;
        float w = 0.f;
        if (s < hi) {
            float c1 = cs[s];
            float c0 = s ? cs[s - 1] : 0.f;
            int ri = min((int)c1, Tn);
            int li = s ? min((int)c0, Tn) : 0;
            int fire = ri - li;
            int extra = fire - 1 > 0 ? fire - 1 : 0;
            float rw = fire > 0 ? c1 - (float)ri : 0.f;
            if (fire > 0 && ri == t) w += rw;
            if (li == t) w += g_alpha[b * Sn + s] * sc - rw - (float)extra;
            if (extra > 0 && li + 1 == t) w += 1.f;
        }
        wbuf[tid] = w;
        __syncthreads();

        const int nend = min(hi - base, 128);
        for (int j = 0; j < nend; j++) {
            float w2 = wbuf[j];
            if (w2 != 0.f) {
                float4 xv = *(const float4*)(x + ((size_t)(b * Sn + base + j)) * Cn + tid4);
                acc.x += w2 * xv.x; acc.y += w2 * xv.y;
                acc.z += w2 * xv.z; acc.w += w2 * xv.w;
            }
        }
        __syncthreads();
    }
    *(float4*)(out + ((size_t)(b * Tn + t)) * Cn + tid4) = acc;
}

// ---------------- launch ----------------
extern "C" void kernel_launch(void* const* d_in, const int* in_sizes, int n_in,
                              void* d_out, int out_size) {
    const float* x      = (const float*)d_in[0];
    const int*   tlen   = (const int*)d_in[2];
    const float* conv_w = (const float*)d_in[4];
    const float* conv_b = (const float*)d_in[5];
    const float* ln_g   = (const float*)d_in[6];
    const float* ln_b   = (const float*)d_in[7];
    const float* lin_w  = (const float*)d_in[8];
    const float* lin_b  = (const float*)d_in[9];

    float* out_main  = (float*)d_out;                          // [B,T,C]
    float* out_alpha = (float*)d_out + (size_t)Bn * Tn * Cn;   // [B,S]

    static bool attr_set = false;
    if (!attr_set) {
        cudaFuncSetAttribute(conv_wino, cudaFuncAttributeMaxDynamicSharedMemorySize, SMEM_W);
        attr_set = true;
    }

    wino_xw<<<XWBLK + WWBLK, 256>>>(x, conv_w);

    conv_wino<<<dim3(Mp / 128, Cn / 128, Bn), 256, SMEM_W>>>(conv_b);

    ln_alpha<<<(Bn * Sn) / 8, 256>>>(ln_g, ln_b, lin_w, lin_b, out_alpha);
    scan_cif<<<Bn, 1024>>>(tlen);
    gather_cif<<<dim3(Tn, Bn), 128>>>(x, out_main);
}

// round 17
// speedup vs baseline: 1.1074x; 1.0160x over previous
#include <cuda_runtime.h>
#include <cuda_fp16.h>
#include <math.h>
#include <stdint.h>

// Problem constants
#define Bn 16
#define Sn 4096
#define Cn 512
#define Kn 5
#define Tn 1024
#define Rn (Cn*Kn)   // 2560
#define Mp (Sn/2)    // 2048 m-pairs per batch

// ---------------- device scratch ----------------
__device__ __align__(16) __half g_xwhi[6ull * Bn * Mp * Cn];
__device__ __align__(16) __half g_xwlo[6ull * Bn * Mp * Cn];
__device__ __align__(16) __half g_wwhi[6 * Cn * Cn];
__device__ __align__(16) __half g_wwlo[6 * Cn * Cn];
__device__ float g_h[(size_t)Bn * Sn * Cn];
__device__ float g_alpha[Bn * Sn];
__device__ float g_csum[Bn * Sn];
__device__ float g_scale[Bn];

__constant__ float c_aw0[6] = {1.f, 1.f, 1.f, 1.f, 1.f, 0.f};   // A^T row 0
__constant__ float c_aw1[6] = {0.f, 1.f, -1.f, 2.f, -2.f, 1.f}; // A^T row 1

// ---------------- helpers ----------------
__device__ __forceinline__ uint32_t smem_u32(const void* p) {
    uint32_t a;
    asm("{ .reg .u64 t; cvta.to.shared.u64 t, %1; cvt.u32.u64 %0, t; }" : "=r"(a) : "l"(p));
    return a;
}
#define SWZ(x) ((x) ^ (((x) >> 3) & 0x70))

__device__ __forceinline__ void cp_async16(uint32_t dst, const void* src) {
    asm volatile("cp.async.cg.shared.global [%0], [%1], 16;"
                 :: "r"(dst), "l"(src) : "memory");
}
__device__ __forceinline__ void cp_commit() {
    asm volatile("cp.async.commit_group;" ::: "memory");
}
__device__ __forceinline__ void cp_wait1() {
    asm volatile("cp.async.wait_group 1;" ::: "memory");
}
__device__ __forceinline__ void cp_wait0() {
    asm volatile("cp.async.wait_group 0;" ::: "memory");
}
__device__ __forceinline__ void ldsm_x4(uint32_t addr, uint32_t& r0, uint32_t& r1,
                                        uint32_t& r2, uint32_t& r3) {
    asm volatile("ldmatrix.sync.aligned.m8n8.x4.shared.b16 {%0,%1,%2,%3}, [%4];"
                 : "=r"(r0), "=r"(r1), "=r"(r2), "=r"(r3) : "r"(addr));
}
__device__ __forceinline__ void mma_f16(float& c0, float& c1, float& c2, float& c3,
                                        uint32_t a0, uint32_t a1, uint32_t a2, uint32_t a3,
                                        uint32_t b0, uint32_t b1) {
    asm volatile(
        "mma.sync.aligned.m16n8k16.row.col.f32.f16.f16.f32 "
        "{%0,%1,%2,%3}, {%4,%5,%6,%7}, {%8,%9}, {%0,%1,%2,%3};"
        : "+f"(c0), "+f"(c1), "+f"(c2), "+f"(c3)
        : "r"(a0), "r"(a1), "r"(a2), "r"(a3), "r"(b0), "r"(b1));
}
__device__ __forceinline__ void split16(float v, __half& h, __half& l) {
    h = __float2half_rn(v);
    l = __float2half_rn(v - __half2float(h));
}

// ---------------- kernel: merged Winograd transforms (x blocks, then w blocks) ----
#define XWBLK (Bn * Mp * 64 / 256)     // 8192 blocks for x transform
#define WWBLK ((Cn * Cn) / 256)        // 1024 blocks for w transform

__global__ void wino_xw(const float* __restrict__ x, const float* __restrict__ w) {
    if (blockIdx.x < XWBLK) {
        // ---- input transform: X̂_j[b][m][ci] over d = x[2m-2 .. 2m+3][ci] ----
        int idx = blockIdx.x * 256 + threadIdx.x;   // < 16*2048*64
        int ci8 = (idx & 63) * 8;
        int m   = (idx >> 6) & (Mp - 1);
        int b   = idx >> 17;

        float d[6][8];
        #pragma unroll
        for (int r = 0; r < 6; r++) {
            int s = 2 * m - 2 + r;
            if (s >= 0 && s < Sn) {
                const float* src = x + ((size_t)(b * Sn + s)) * Cn + ci8;
                float4 a = *(const float4*)src;
                float4 c = *(const float4*)(src + 4);
                d[r][0]=a.x; d[r][1]=a.y; d[r][2]=a.z; d[r][3]=a.w;
                d[r][4]=c.x; d[r][5]=c.y; d[r][6]=c.z; d[r][7]=c.w;
            } else {
                #pragma unroll
                for (int q = 0; q < 8; q++) d[r][q] = 0.f;
            }
        }

        __half oh[6][8], ol[6][8];
        #pragma unroll
        for (int q = 0; q < 8; q++) {
            float d0=d[0][q], d1=d[1][q], d2=d[2][q], d3=d[3][q], d4=d[4][q], d5=d[5][q];
            float t0 = d0 - 1.25f*d2 + 0.25f*d4;
            float t1 = (2.f/3.f)*(d1 + d2) - (1.f/6.f)*(d3 + d4);
            float t2 = (2.f/3.f)*(d2 - d1) + (1.f/6.f)*(d3 - d4);
            float t3 = (1.f/12.f)*(d3 - d1) + (1.f/24.f)*(d4 - d2);
            float t4 = (1.f/12.f)*(d1 - d3) + (1.f/24.f)*(d4 - d2);
            float t5 = 4.f*d1 - 5.f*d3 + d5;
            split16(t0, oh[0][q], ol[0][q]);
            split16(t1, oh[1][q], ol[1][q]);
            split16(t2, oh[2][q], ol[2][q]);
            split16(t3, oh[3][q], ol[3][q]);
            split16(t4, oh[4][q], ol[4][q]);
            split16(t5, oh[5][q], ol[5][q]);
        }
        #pragma unroll
        for (int j = 0; j < 6; j++) {
            size_t o = ((size_t)((j * Bn + b) * Mp + m)) * Cn + ci8;
            *(uint4*)(g_xwhi + o) = *(uint4*)oh[j];
            *(uint4*)(g_xwlo + o) = *(uint4*)ol[j];
        }
    } else {
        // ---- weight transform: Ŵ_j[co][ci] = G[j] · w[co][ci][0..4] ----
        int idx = (blockIdx.x - XWBLK) * 256 + threadIdx.x;   // < 512*512
        int co = idx >> 9;
        int ci = idx & 511;
        const float* wp = w + (size_t)co * Rn + ci * Kn;
        float w0 = wp[0], w1 = wp[1], w2 = wp[2], w3 = wp[3], w4 = wp[4];
        float tw[6];
        tw[0] = w0;
        tw[1] = w0 + w1 + w2 + w3 + w4;
        tw[2] = w0 - w1 + w2 - w3 + w4;
        tw[3] = w0 + 2.f*w1 + 4.f*w2 + 8.f*w3 + 16.f*w4;
        tw[4] = w0 - 2.f*w1 + 4.f*w2 - 8.f*w3 + 16.f*w4;
        tw[5] = w4;
        #pragma unroll
        for (int j = 0; j < 6; j++) {
            __half h, l;
            split16(tw[j], h, l);
            size_t o = ((size_t)(j * Cn + co)) * Cn + ci;
            g_wwhi[o] = h;
            g_wwlo[o] = l;
        }
    }
}

// ---------------- Winograd GEMM: 128 m-pairs x 128 co, 3-stage single-sync -------
// 48 chunk-iters (6 j x 8 K-chunks of 64 ci). 8 warps 2(M) x 4(N); warp tile 64x32.
#define ST 16384            // each of Ah, Al, Bh, Bl: 128 rows x 128B
#define STG_W (4*ST)        // 65536
#define NSTG 3
#define SMEM_W (NSTG*STG_W) // 196608
#define NCC 48

__global__ __launch_bounds__(256, 1)
void conv_wino(const float* __restrict__ cbias) {
    extern __shared__ char smem[];
    const uint32_t sbase = smem_u32(smem);
    const int tid  = threadIdx.x;
    const int lane = tid & 31;
    const int wid  = tid >> 5;
    const int b     = blockIdx.z;
    const int mBase = blockIdx.x * 128;   // m-pair base
    const int nBase = blockIdx.y * 128;   // co base
    const int mW = (wid >> 2) * 64;
    const int nW = (wid & 3) * 32;

    const uint4* xwhi = (const uint4*)g_xwhi;
    const uint4* xwlo = (const uint4*)g_xwlo;
    const uint4* wwhi = (const uint4*)g_wwhi;
    const uint4* wwlo = (const uint4*)g_wwlo;

    auto load_chunk = [&](int cc) {
        const int j   = cc >> 3;
        const int u0  = (cc & 7) * 8;     // uint4 offset within 512-ci row
        const uint32_t stOff = sbase + (cc % NSTG) * STG_W;
        // A: 128 m-pair rows x 64 ci, hi+lo: 2048 uint4, 8/thread
        #pragma unroll
        for (int i = 0; i < 8; i++) {
            int q   = tid + (i << 8);
            int a2  = q >> 10;
            int rem = q & 1023;
            int row = rem >> 3, p = rem & 7;
            const uint4* src = a2 ? xwlo : xwhi;
            cp_async16(stOff + a2 * ST + SWZ(row * 128 + p * 16),
                       src + ((size_t)((j * Bn + b) * Mp + mBase + row)) * 64 + u0 + p);
        }
        // B: 128 co rows x 64 ci, hi+lo: 2048 uint4, 8/thread
        #pragma unroll
        for (int i = 0; i < 8; i++) {
            int q   = tid + (i << 8);
            int a2  = q >> 10;
            int rem = q & 1023;
            int row = rem >> 3, p = rem & 7;
            const uint4* src = a2 ? wwlo : wwhi;
            cp_async16(stOff + 2 * ST + a2 * ST + SWZ(row * 128 + p * 16),
                       src + ((size_t)(j * Cn + nBase + row)) * 64 + u0 + p);
        }
        cp_commit();
    };

    float accJ[4][4][4], acc0[4][4][4], acc1[4][4][4];
    #pragma unroll
    for (int i = 0; i < 4; i++)
        #pragma unroll
        for (int n = 0; n < 4; n++)
            #pragma unroll
            for (int k = 0; k < 4; k++) {
                accJ[i][n][k] = 0.f; acc0[i][n][k] = 0.f; acc1[i][n][k] = 0.f;
            }

    load_chunk(0);
    load_chunk(1);

    const int aRow = (lane & 15);
    const int aSub = (lane >> 4) * 16;
    const int bRow = (lane & 7) + ((lane & 16) >> 1);
    const int bSub = ((lane >> 3) & 1) * 16;

    for (int cc = 0; cc < NCC; cc++) {
        if (cc == NCC - 1) cp_wait0(); else cp_wait1();  // chunk cc resident
        __syncthreads();          // publish buf cc; all warps done with buf cc-1
        if (cc + 2 < NCC) load_chunk(cc + 2);   // writes buf (cc-1)%3 — safe

        const uint32_t aBase = sbase + (cc % NSTG) * STG_W;
        const uint32_t bBase = aBase + 2 * ST;

        #pragma unroll
        for (int kk = 0; kk < 4; kk++) {
            const int kb = kk * 32;
            uint32_t ah[4][4], al[4][4];
            #pragma unroll
            for (int mt = 0; mt < 4; mt++) {
                int row = mW + mt * 16 + aRow;
                uint32_t off = SWZ(row * 128 + kb + aSub);
                ldsm_x4(aBase + off,      ah[mt][0], ah[mt][1], ah[mt][2], ah[mt][3]);
                ldsm_x4(aBase + ST + off, al[mt][0], al[mt][1], al[mt][2], al[mt][3]);
            }
            #pragma unroll
            for (int nt2 = 0; nt2 < 2; nt2++) {
                uint32_t bh[2][2], bl[2][2];
                int row = nW + nt2 * 16 + bRow;
                uint32_t off = SWZ(row * 128 + kb + bSub);
                ldsm_x4(bBase + off,      bh[0][0], bh[0][1], bh[1][0], bh[1][1]);
                ldsm_x4(bBase + ST + off, bl[0][0], bl[0][1], bl[1][0], bl[1][1]);
                #pragma unroll
                for (int mt = 0; mt < 4; mt++)
                    #pragma unroll
                    for (int n = 0; n < 2; n++) {
                        float* cc2 = accJ[mt][nt2 * 2 + n];
                        mma_f16(cc2[0], cc2[1], cc2[2], cc2[3],
                                ah[mt][0], ah[mt][1], ah[mt][2], ah[mt][3],
                                bh[n][0], bh[n][1]);
                    }
                #pragma unroll
                for (int mt = 0; mt < 4; mt++)
                    #pragma unroll
                    for (int n = 0; n < 2; n++) {
                        float* cc2 = accJ[mt][nt2 * 2 + n];
                        mma_f16(cc2[0], cc2[1], cc2[2], cc2[3],
                                ah[mt][0], ah[mt][1], ah[mt][2], ah[mt][3],
                                bl[n][0], bl[n][1]);
                    }
                #pragma unroll
                for (int mt = 0; mt < 4; mt++)
                    #pragma unroll
                    for (int n = 0; n < 2; n++) {
                        float* cc2 = accJ[mt][nt2 * 2 + n];
                        mma_f16(cc2[0], cc2[1], cc2[2], cc2[3],
                                al[mt][0], al[mt][1], al[mt][2], al[mt][3],
                                bh[n][0], bh[n][1]);
                    }
            }
        }

        // fold completed j-GEMM into output accumulators (A^T combine)
        if ((cc & 7) == 7) {
            const int j = cc >> 3;
            const float w0 = c_aw0[j], w1 = c_aw1[j];
            #pragma unroll
            for (int mt = 0; mt < 4; mt++)
                #pragma unroll
                for (int n = 0; n < 4; n++)
                    #pragma unroll
                    for (int k = 0; k < 4; k++) {
                        float v = accJ[mt][n][k];
                        acc0[mt][n][k] += w0 * v;
                        acc1[mt][n][k] += w1 * v;
                        accJ[mt][n][k] = 0.f;
                    }
        }
    }

    // ---- epilogue: H[2m] = acc0 + bias, H[2m+1] = acc1 + bias ----
    #pragma unroll
    for (int nt = 0; nt < 4; nt++) {
        const int col = nBase + nW + nt * 8 + (lane & 3) * 2;
        const float b0 = cbias[col], b1 = cbias[col + 1];
        #pragma unroll
        for (int mt = 0; mt < 4; mt++) {
            const int mp = mBase + mW + mt * 16 + (lane >> 2);   // m-pair index
            float* p0 = g_h + ((size_t)(b * Sn + 2 * mp)) * Cn + col;
            p0[0]            = acc0[mt][nt][0] + b0;  p0[1]            = acc0[mt][nt][1] + b1;
            p0[Cn]           = acc1[mt][nt][0] + b0;  p0[Cn + 1]       = acc1[mt][nt][1] + b1;
            p0[16 * Cn]      = acc0[mt][nt][2] + b0;  p0[16 * Cn + 1]  = acc0[mt][nt][3] + b1;
            p0[17 * Cn]      = acc1[mt][nt][2] + b0;  p0[17 * Cn + 1]  = acc1[mt][nt][3] + b1;
        }
    }
}

// ---------------- kernel: LayerNorm + ReLU + Linear + sigmoid (float4 loads) ----
__global__ void ln_alpha(const float* __restrict__ lng, const float* __restrict__ lnb,
                         const float* __restrict__ lw,  const float* __restrict__ lb,
                         float* __restrict__ alpha_out) {
    const int warp = threadIdx.x >> 5;
    const int lane = threadIdx.x & 31;
    const int row  = blockIdx.x * 8 + warp;
    const float4* hr = (const float4*)(g_h + (size_t)row * Cn);
    const float4* g4 = (const float4*)lng;
    const float4* b4 = (const float4*)lnb;
    const float4* w4 = (const float4*)lw;

    float4 v[4];
    float sum = 0.f;
    #pragma unroll
    for (int j = 0; j < 4; j++) {
        v[j] = hr[lane + j * 32];
        sum += (v[j].x + v[j].y) + (v[j].z + v[j].w);
    }
    #pragma unroll
    for (int o = 16; o; o >>= 1) sum += __shfl_xor_sync(0xffffffffu, sum, o);
    const float mu = sum * (1.0f / Cn);

    float vs = 0.f;
    #pragma unroll
    for (int j = 0; j < 4; j++) {
        float dx = v[j].x - mu, dy = v[j].y - mu, dz = v[j].z - mu, dw = v[j].w - mu;
        vs += dx * dx + dy * dy + dz * dz + dw * dw;
    }
    #pragma unroll
    for (int o = 16; o; o >>= 1) vs += __shfl_xor_sync(0xffffffffu, vs, o);
    const float rstd = rsqrtf(vs * (1.0f / Cn) + 1e-5f);

    float dot = 0.f;
    #pragma unroll
    for (int j = 0; j < 4; j++) {
        const int c4 = lane + j * 32;
        float4 gg = g4[c4], bb = b4[c4], ww = w4[c4];
        float h0 = fmaxf((v[j].x - mu) * rstd * gg.x + bb.x, 0.f);
        float h1 = fmaxf((v[j].y - mu) * rstd * gg.y + bb.y, 0.f);
        float h2 = fmaxf((v[j].z - mu) * rstd * gg.z + bb.z, 0.f);
        float h3 = fmaxf((v[j].w - mu) * rstd * gg.w + bb.w, 0.f);
        dot += h0 * ww.x + h1 * ww.y + h2 * ww.z + h3 * ww.w;
    }
    #pragma unroll
    for (int o = 16; o; o >>= 1) dot += __shfl_xor_sync(0xffffffffu, dot, o);

    if (lane == 0) {
        float a = 1.0f / (1.0f + expf(-(dot + lb[0])));
        g_alpha[row]   = a;
        alpha_out[row] = a;
    }
}

// ---------------- kernel: per-batch alpha-sum, rescale, inclusive cumsum ----------------
__global__ void scan_cif(const int* __restrict__ tlen) {
    __shared__ float wsum[32];
    __shared__ float woff[32];
    __shared__ float sscale;

    const int b   = blockIdx.x;
    const int tid = threadIdx.x;
    const int wid  = tid >> 5;
    const int lane = tid & 31;
    const float* ar = g_alpha + b * Sn;

    float v0 = ar[tid * 4 + 0], v1 = ar[tid * 4 + 1];
    float v2 = ar[tid * 4 + 2], v3 = ar[tid * 4 + 3];
    float tsum = v0 + v1 + v2 + v3;

    float r = tsum;
    #pragma unroll
    for (int o = 16; o; o >>= 1) r += __shfl_xor_sync(0xffffffffu, r, o);
    if (lane == 0) wsum[wid] = r;
    __syncthreads();
    if (tid == 0) {
        float a = 0.f;
        for (int i = 0; i < 32; i++) a += wsum[i];
        sscale = ((float)tlen[b] + 1e-4f) / a;
    }
    __syncthreads();
    const float sc = sscale;

    float p0 = v0 * sc;
    float p1 = p0 + v1 * sc;
    float p2 = p1 + v2 * sc;
    float p3 = p2 + v3 * sc;

    float inc = p3;
    #pragma unroll
    for (int o = 1; o < 32; o <<= 1) {
        float t = __shfl_up_sync(0xffffffffu, inc, o);
        if (lane >= o) inc += t;
    }
    if (lane == 31) wsum[wid] = inc;
    __syncthreads();
    if (tid < 32) {
        float t = wsum[tid];
        float i2 = t;
        #pragma unroll
        for (int o = 1; o < 32; o <<= 1) {
            float u = __shfl_up_sync(0xffffffffu, i2, o);
            if (tid >= o) i2 += u;
        }
        woff[tid] = i2 - t;
    }
    __syncthreads();

    const float off = woff[wid] + (inc - p3);
    float* cs = g_csum + b * Sn + tid * 4;
    cs[0] = off + p0; cs[1] = off + p1; cs[2] = off + p2; cs[3] = off + p3;
    if (tid == 0) g_scale[b] = sc;
}

// ---------------- kernel: CIF gather v2 (warp-parallel weight precompute) --------
__global__ void gather_cif(const float* __restrict__ x, float* __restrict__ out) {
    const int t = blockIdx.x;
    const int b = blockIdx.y;
    const float* cs = g_csum + b * Sn;
    const float sc = g_scale[b];
    const int tid = threadIdx.x;

    const float loV = (float)(t - 1), hiV = (float)(t + 1);
    int l = 0, r = Sn;
    while (l < r) { int m = (l + r) >> 1; if (cs[m] < loV) l = m + 1; else r = m; }
    const int lo = l;
    l = lo; r = Sn;
    while (l < r) { int m = (l + r) >> 1; if (cs[m] < hiV) l = m + 1; else r = m; }
    const int hi = min(l + 1, Sn);

    __shared__ float wbuf[128];
    const int tid4 = tid * 4;
    float4 acc = make_float4(0.f, 0.f, 0.f, 0.f);

    for (int base = lo; base < hi; base += 128) {
        int s = base + tid;
        float w = 0.f;
        if (s < hi) {
            float c1 = cs[s];
            float c0 = s ? cs[s - 1] : 0.f;
            int ri = min((int)c1, Tn);
            int li = s ? min((int)c0, Tn) : 0;
            int fire = ri - li;
            int extra = fire - 1 > 0 ? fire - 1 : 0;
            float rw = fire > 0 ? c1 - (float)ri : 0.f;
            if (fire > 0 && ri == t) w += rw;
            if (li == t) w += g_alpha[b * Sn + s] * sc - rw - (float)extra;
            if (extra > 0 && li + 1 == t) w += 1.f;
        }
        wbuf[tid] = w;
        __syncthreads();

        const int nend = min(hi - base, 128);
        for (int j = 0; j < nend; j++) {
            float w2 = wbuf[j];
            if (w2 != 0.f) {
                float4 xv = *(const float4*)(x + ((size_t)(b * Sn + base + j)) * Cn + tid4);
                acc.x += w2 * xv.x; acc.y += w2 * xv.y;
                acc.z += w2 * xv.z; acc.w += w2 * xv.w;
            }
        }
        __syncthreads();
    }
    *(float4*)(out + ((size_t)(b * Tn + t)) * Cn + tid4) = acc;
}

// ---------------- launch ----------------
extern "C" void kernel_launch(void* const* d_in, const int* in_sizes, int n_in,
                              void* d_out, int out_size) {
    const float* x      = (const float*)d_in[0];
    const int*   tlen   = (const int*)d_in[2];
    const float* conv_w = (const float*)d_in[4];
    const float* conv_b = (const float*)d_in[5];
    const float* ln_g   = (const float*)d_in[6];
    const float* ln_b   = (const float*)d_in[7];
    const float* lin_w  = (const float*)d_in[8];
    const float* lin_b  = (const float*)d_in[9];

    float* out_main  = (float*)d_out;                          // [B,T,C]
    float* out_alpha = (float*)d_out + (size_t)Bn * Tn * Cn;   // [B,S]

    static bool attr_set = false;
    if (!attr_set) {
        cudaFuncSetAttribute(conv_wino, cudaFuncAttributeMaxDynamicSharedMemorySize, SMEM_W);
        attr_set = true;
    }

    wino_xw<<<XWBLK + WWBLK, 256>>>(x, conv_w);

    conv_wino<<<dim3(Mp / 128, Cn / 128, Bn), 256, SMEM_W>>>(conv_b);

    ln_alpha<<<(Bn * Sn) / 8, 256>>>(ln_g, ln_b, lin_w, lin_b, out_alpha);
    scan_cif<<<Bn, 1024>>>(tlen);
    gather_cif<<<dim3(Tn, Bn), 128>>>(x, out_main);
}